// round 16
// baseline (speedup 1.0000x reference)
#include <cuda_runtime.h>
#include <cuda_bf16.h>
#include <cuda_fp16.h>
#include <cstdint>

#define N_NODES 40000
#define N_EDGES 640000
#define HIDDEN  128
#define N_GRAPHS 256
#define N_CLASSES 5

#define GEMM_BLOCKS 313          // ceil(40000/128)
#define CNT_BLOCKS  625          // 640000/4/256
#define FILL_BLOCKS 1250         // 640000/2/256
#define CSR_CAP     (N_EDGES + 7 * N_NODES)   // segments padded to mult of 8 (920000)
#define PREF_BLOCKS 899          // ceil(CSR_CAP/4/256)  sentinel prefill
#define WF_PER_LAYER 4096        // 8 ksteps x 16 ntiles x 32 lanes (uint4 each)

// ---------------- scratch (static device globals; no runtime alloc) ----------
// NOTE: g_deg is zero at every launch entry: zero-initialized statically, and
// scan_kernel re-zeroes it after consuming (deterministic across graph replays).
__device__ __align__(16) __half g_y16[(N_NODES + 1) * HIDDEN];  // y1'/y2'/z3 (+ zero row)
__device__ __align__(16) __half g_h16[(N_NODES + 1) * HIDDEN];  // h1 / h2' (+ zero row)
__device__ __align__(16) float  g_dinv[N_NODES];
__device__ __align__(16) int    g_deg[N_NODES];
__device__ __align__(16) int    g_rowptr[N_NODES + 4];
__device__ __align__(16) int    g_cursor[N_NODES];
__device__ __align__(16) int    g_csrc[CSR_CAP + 16];
__device__ float g_s[N_GRAPHS * HIDDEN];    // pooled means
__device__ float g_WC[HIDDEN * N_CLASSES];  // W3 @ Wl
__device__ float g_bc[N_CLASSES];           // b3 @ Wl + bl
// fp16 W fragments for m16n8k16 MMA (W = hi + lo split), per layer:
// [ (ks*16 + nt)*32 + lane ] -> uint4 { b0_hi, b1_hi, b0_lo, b1_lo } (each = 2 halves)
__device__ __align__(16) uint4 g_wf16[2][WF_PER_LAYER];

// ---------------- helpers -----------------------------------------------------
__device__ __forceinline__ void mma_f16(float* d,
                                        unsigned a0, unsigned a1, unsigned a2, unsigned a3,
                                        unsigned b0, unsigned b1)
{
    asm volatile(
        "mma.sync.aligned.m16n8k16.row.col.f32.f16.f16.f32 "
        "{%0,%1,%2,%3}, {%4,%5,%6,%7}, {%8,%9}, {%0,%1,%2,%3};"
        : "+f"(d[0]), "+f"(d[1]), "+f"(d[2]), "+f"(d[3])
        : "r"(a0), "r"(a1), "r"(a2), "r"(a3), "r"(b0), "r"(b1));
}

__device__ __forceinline__ float2 h2f2(unsigned u) {
    __half2 h = *reinterpret_cast<__half2*>(&u);
    return __half22float2(h);
}

__device__ __forceinline__ __half2 u2h(unsigned u) {
    return *reinterpret_cast<__half2*>(&u);
}

__device__ __forceinline__ unsigned packh2(float a, float b) {
    __half2 h = __floats2half2_rn(a, b);     // a -> low half, b -> high half
    return *reinterpret_cast<unsigned*>(&h);
}

// ---------------- GEMM body: fp16 A (exact) x (W_hi + W_lo), fp32 acc ---------
// Y16 = half( dinv[row] * (A @ W) ).  A staged fp16 in smem (128x128, pad 8 halves).
__device__ __forceinline__ void gemm_body16(int bid,
                                            const float* __restrict__ A32,
                                            const __half* __restrict__ A16,
                                            const uint4* __restrict__ wfrag,
                                            __half* __restrict__ Y16)
{
    __shared__ __align__(16) unsigned s_a[128 * 68];   // fp16 tile: 68 words (136 halves)/row

    int tid  = threadIdx.x;
    int warp = tid >> 5;
    int lane = tid & 31;
    int row0 = bid * 128;
    int wrow = row0 + warp * 16;

    // stage A as fp16
    if (A32) {
        #pragma unroll
        for (int j = 0; j < 16; j++) {
            int idx = tid + 256 * j;            // 0..4095 float4s
            int r = idx >> 5;                   // 0..127
            int c4 = (idx & 31) * 4;            // 0..124 (halves/floats)
            int gr = row0 + r;
            float4 v = make_float4(0.f, 0.f, 0.f, 0.f);
            if (gr < N_NODES)
                v = *reinterpret_cast<const float4*>(&A32[gr * 128 + c4]);
            uint2 o;
            o.x = packh2(v.x, v.y);
            o.y = packh2(v.z, v.w);
            *reinterpret_cast<uint2*>(&s_a[r * 68 + (idx & 31) * 2]) = o;
        }
    } else {
        #pragma unroll
        for (int j = 0; j < 8; j++) {
            int idx = tid + 256 * j;            // 0..2047 uint4s
            int r = idx >> 4;                   // 0..127
            int c16 = idx & 15;                 // uint4 within row (8 halves each)
            int gr = row0 + r;
            uint4 v = make_uint4(0u, 0u, 0u, 0u);
            if (gr < N_NODES)
                v = *reinterpret_cast<const uint4*>(&A16[gr * 128 + c16 * 8]);
            *reinterpret_cast<uint4*>(&s_a[r * 68 + c16 * 4]) = v;
        }
    }
    __syncthreads();

    float acc[64];
    #pragma unroll
    for (int i = 0; i < 64; i++) acc[i] = 0.f;

    int rw0 = (warp * 16 + (lane >> 2)) * 68;
    int rw1 = rw0 + 8 * 68;

    #pragma unroll
    for (int ks = 0; ks < 8; ks++) {
        int cw = ks * 8 + (lane & 3);
        unsigned a0 = s_a[rw0 + cw];
        unsigned a1 = s_a[rw1 + cw];
        unsigned a2 = s_a[rw0 + cw + 4];
        unsigned a3 = s_a[rw1 + cw + 4];

        const uint4* bk = wfrag + ks * 512 + lane;
        #pragma unroll
        for (int nt = 0; nt < 16; nt++) {
            uint4 b = __ldg(bk + nt * 32);   // {b0_hi, b1_hi, b0_lo, b1_lo}
            float* d = acc + nt * 4;
            mma_f16(d, a0, a1, a2, a3, b.x, b.y);   // A x W_hi
            mma_f16(d, a0, a1, a2, a3, b.z, b.w);   // A x W_lo
        }
    }

    if (wrow < N_NODES) {
        int r0 = wrow + (lane >> 2);
        int r1 = r0 + 8;
        float d0 = g_dinv[r0];
        float d1 = g_dinv[r1];
        #pragma unroll
        for (int nt = 0; nt < 16; nt++) {
            int col = nt * 8 + (lane & 3) * 2;
            __half2 p0 = __floats2half2_rn(d0 * acc[nt * 4 + 0], d0 * acc[nt * 4 + 1]);
            __half2 p1 = __floats2half2_rn(d1 * acc[nt * 4 + 2], d1 * acc[nt * 4 + 3]);
            *reinterpret_cast<__half2*>(&Y16[r0 * 128 + col]) = p0;
            *reinterpret_cast<__half2*>(&Y16[r1 * 128 + col]) = p1;
        }
    }
}

// ---------------- prep: wfrag + csrc sentinel prefill + deg count + head ------
__global__ __launch_bounds__(256) void prep_kernel(
    const float* __restrict__ W1, const float* __restrict__ W2,
    const float* __restrict__ W3, const float* __restrict__ b3,
    const float* __restrict__ Wl, const float* __restrict__ bl,
    const int* __restrict__ ei)
{
    const int B_PREF = 32;                       // 2 layers x 4096 frags / 256
    const int B_CNT  = B_PREF + PREF_BLOCKS;
    const int B_HEAD = B_CNT + CNT_BLOCKS;
    const int B_ZROW = B_HEAD + 3;

    if (blockIdx.x < B_PREF) {
        int t = blockIdx.x * 256 + threadIdx.x;  // 0..8191
        int layer = t >> 12;
        int r = t & 4095;                 // (ks*16 + nt)*32 + lane
        int ks   = r >> 9;                // 0..7
        int nt   = (r >> 5) & 15;
        int lane = r & 31;
        int k0 = ks * 16 + (lane & 3) * 2;
        int n  = nt * 8 + (lane >> 2);
        const float* W = layer ? W2 : W1;
        float w00 = W[k0 * HIDDEN + n];
        float w01 = W[(k0 + 1) * HIDDEN + n];
        float w10 = W[(k0 + 8) * HIDDEN + n];
        float w11 = W[(k0 + 9) * HIDDEN + n];
        float h00 = __half2float(__float2half_rn(w00));
        float h01 = __half2float(__float2half_rn(w01));
        float h10 = __half2float(__float2half_rn(w10));
        float h11 = __half2float(__float2half_rn(w11));
        uint4 o;
        o.x = packh2(h00, h01);
        o.y = packh2(h10, h11);
        o.z = packh2(w00 - h00, w01 - h01);
        o.w = packh2(w10 - h10, w11 - h11);
        g_wf16[layer][r] = o;
    } else if (blockIdx.x < B_CNT) {
        int t = (blockIdx.x - B_PREF) * 256 + threadIdx.x;   // int4 index
        if (t < CSR_CAP / 4)
            *reinterpret_cast<int4*>(&g_csrc[t * 4]) =
                make_int4(N_NODES, N_NODES, N_NODES, N_NODES);
    } else if (blockIdx.x < B_HEAD) {
        int e4 = ((blockIdx.x - B_CNT) * 256 + threadIdx.x) * 4;
        if (e4 < N_EDGES) {
            int4 d = *reinterpret_cast<const int4*>(&ei[N_EDGES + e4]);
            atomicAdd(&g_deg[d.x], 1);
            atomicAdd(&g_deg[d.y], 1);
            atomicAdd(&g_deg[d.z], 1);
            atomicAdd(&g_deg[d.w], 1);
        }
    } else if (blockIdx.x < B_ZROW) {
        int t = (blockIdx.x - B_HEAD) * 256 + threadIdx.x;
        if (t < HIDDEN * N_CLASSES) {
            int j = t / N_CLASSES, c = t % N_CLASSES;
            float s = 0.f;
            for (int k = 0; k < HIDDEN; k++) s = fmaf(W3[j * HIDDEN + k], Wl[k * N_CLASSES + c], s);
            g_WC[t] = s;
        } else if (t < HIDDEN * N_CLASSES + N_CLASSES) {
            int c = t - HIDDEN * N_CLASSES;
            float s = bl[c];
            for (int k = 0; k < HIDDEN; k++) s = fmaf(b3[k], Wl[k * N_CLASSES + c], s);
            g_bc[c] = s;
        }
    } else {
        // zero the sentinel rows (row N_NODES) of both fp16 gather buffers
        int t = threadIdx.x;
        if (t < 64)
            reinterpret_cast<unsigned*>(&g_y16[N_NODES * HIDDEN])[t] = 0u;
        else if (t < 128)
            reinterpret_cast<unsigned*>(&g_h16[N_NODES * HIDDEN])[t - 64] = 0u;
    }
}

// ---------------- scan: rowptr padded to mult-of-8; re-zeroes deg -------------
__global__ void scan_kernel() {
    const int NT = 1024;
    int tid = threadIdx.x;
    int lane = tid & 31, wid = tid >> 5;
    __shared__ int wsum[32];
    __shared__ int s_carry;
    if (tid == 0) s_carry = 0;
    __syncthreads();
    for (int base = 0; base < N_NODES; base += NT * 4) {
        int i4 = base + tid * 4;
        int4 v = make_int4(0, 0, 0, 0);
        if (i4 < N_NODES)
            v = *reinterpret_cast<const int4*>(&g_deg[i4]);
        int4 p = make_int4((v.x + 7) & ~7, (v.y + 7) & ~7,
                           (v.z + 7) & ~7, (v.w + 7) & ~7);
        int s = p.x + p.y + p.z + p.w;
        int x = s;
        #pragma unroll
        for (int d = 1; d < 32; d <<= 1) {
            int t = __shfl_up_sync(0xffffffffu, x, d);
            if (lane >= d) x += t;
        }
        if (lane == 31) wsum[wid] = x;
        __syncthreads();
        if (wid == 0) {
            int w = wsum[lane];
            #pragma unroll
            for (int d = 1; d < 32; d <<= 1) {
                int t = __shfl_up_sync(0xffffffffu, w, d);
                if (lane >= d) w += t;
            }
            wsum[lane] = w;
        }
        __syncthreads();
        int carry = s_carry;
        int woff = (wid == 0) ? 0 : wsum[wid - 1];
        int incl = x + woff + carry;
        int e0 = incl - s;
        if (i4 < N_NODES) {
            int4 rp = make_int4(e0, e0 + p.x, e0 + p.x + p.y, e0 + p.x + p.y + p.z);
            *reinterpret_cast<int4*>(&g_rowptr[i4]) = rp;
            *reinterpret_cast<int4*>(&g_cursor[i4]) = rp;
            float4 dv = make_float4(rsqrtf((float)(v.x + 1)), rsqrtf((float)(v.y + 1)),
                                    rsqrtf((float)(v.z + 1)), rsqrtf((float)(v.w + 1)));
            *reinterpret_cast<float4*>(&g_dinv[i4]) = dv;
            // restore the launch-entry invariant deg == 0 for the next call
            *reinterpret_cast<int4*>(&g_deg[i4]) = make_int4(0, 0, 0, 0);
        }
        __syncthreads();
        if (tid == NT - 1) s_carry = incl;
        __syncthreads();
    }
    if (tid == 0) g_rowptr[N_NODES] = s_carry;
}

// ---------------- fused: GEMM layer-1 (x fp32 -> fp16) + CSR fill -------------
__global__ __launch_bounds__(256) void gemm1_fill_kernel(
    const float* __restrict__ A, const uint4* __restrict__ wfrag,
    __half* __restrict__ Y16, const int* __restrict__ ei)
{
    if (blockIdx.x < GEMM_BLOCKS) {
        gemm_body16(blockIdx.x, A, (const __half*)nullptr, wfrag, Y16);
    } else {
        int e2 = ((blockIdx.x - GEMM_BLOCKS) * 256 + threadIdx.x) * 2;
        if (e2 < N_EDGES) {
            int2 s = *reinterpret_cast<const int2*>(&ei[e2]);
            int2 d = *reinterpret_cast<const int2*>(&ei[N_EDGES + e2]);
            int p0 = atomicAdd(&g_cursor[d.x], 1);
            int p1 = atomicAdd(&g_cursor[d.y], 1);
            g_csrc[p0] = s.x;
            g_csrc[p1] = s.y;
        }
    }
}

// ---------------- standalone GEMM (layer 2, fp16 input) -----------------------
__global__ __launch_bounds__(256) void gemm_f16_kernel(
    const __half* __restrict__ A16, const uint4* __restrict__ wfrag,
    __half* __restrict__ Y16)
{
    gemm_body16(blockIdx.x, (const float*)nullptr, A16, wfrag, Y16);
}

// ---------------- Aggregation: 1 warp/node, 16-edge load window ---------------
// Rows pre-scaled by dinv[src]:  r = dinv[i] * (self + sum_in row[s]) + b
// out16: fp16 result, times dinv[i] iff scale_out16.
__global__ __launch_bounds__(256) void agg_kernel(
    const __half* __restrict__ y16, __half* __restrict__ out16,
    const float* __restrict__ bias, int do_relu, int scale_out16)
{
    int warp = (blockIdx.x * blockDim.x + threadIdx.x) >> 5;
    int lane = threadIdx.x & 31;
    if (warp >= N_NODES) return;

    const uint2* y8 = reinterpret_cast<const uint2*>(y16);   // 4 halves per lane
    float di = g_dinv[warp];

    uint2 sv = y8[warp * 32 + lane];
    float2 sa = h2f2(sv.x), sb = h2f2(sv.y);
    float4 accA = make_float4(sa.x, sa.y, sb.x, sb.y);
    float4 accB = make_float4(0.f, 0.f, 0.f, 0.f);

    int e   = g_rowptr[warp];
    int end = g_rowptr[warp + 1];

    // 16-edge window: issue all 16 gathers before any tree work (MLP=16)
    for (; e + 16 <= end; e += 16) {
        int4 i0 = *reinterpret_cast<const int4*>(&g_csrc[e]);
        int4 i1 = *reinterpret_cast<const int4*>(&g_csrc[e + 4]);
        int4 i2 = *reinterpret_cast<const int4*>(&g_csrc[e + 8]);
        int4 i3 = *reinterpret_cast<const int4*>(&g_csrc[e + 12]);
        uint2 v0 = __ldg(&y8[i0.x * 32 + lane]);
        uint2 v1 = __ldg(&y8[i0.y * 32 + lane]);
        uint2 v2 = __ldg(&y8[i0.z * 32 + lane]);
        uint2 v3 = __ldg(&y8[i0.w * 32 + lane]);
        uint2 v4 = __ldg(&y8[i1.x * 32 + lane]);
        uint2 v5 = __ldg(&y8[i1.y * 32 + lane]);
        uint2 v6 = __ldg(&y8[i1.z * 32 + lane]);
        uint2 v7 = __ldg(&y8[i1.w * 32 + lane]);
        uint2 w0 = __ldg(&y8[i2.x * 32 + lane]);
        uint2 w1 = __ldg(&y8[i2.y * 32 + lane]);
        uint2 w2 = __ldg(&y8[i2.z * 32 + lane]);
        uint2 w3 = __ldg(&y8[i2.w * 32 + lane]);
        uint2 w4 = __ldg(&y8[i3.x * 32 + lane]);
        uint2 w5 = __ldg(&y8[i3.y * 32 + lane]);
        uint2 w6 = __ldg(&y8[i3.z * 32 + lane]);
        uint2 w7 = __ldg(&y8[i3.w * 32 + lane]);

        __half2 ax = __hadd2(__hadd2(__hadd2(u2h(v0.x), u2h(v1.x)), __hadd2(u2h(v2.x), u2h(v3.x))),
                             __hadd2(__hadd2(u2h(v4.x), u2h(v5.x)), __hadd2(u2h(v6.x), u2h(v7.x))));
        __half2 ay = __hadd2(__hadd2(__hadd2(u2h(v0.y), u2h(v1.y)), __hadd2(u2h(v2.y), u2h(v3.y))),
                             __hadd2(__hadd2(u2h(v4.y), u2h(v5.y)), __hadd2(u2h(v6.y), u2h(v7.y))));
        float2 fax = __half22float2(ax);
        float2 fay = __half22float2(ay);
        accA.x += fax.x; accA.y += fax.y; accA.z += fay.x; accA.w += fay.y;

        __half2 bx = __hadd2(__hadd2(__hadd2(u2h(w0.x), u2h(w1.x)), __hadd2(u2h(w2.x), u2h(w3.x))),
                             __hadd2(__hadd2(u2h(w4.x), u2h(w5.x)), __hadd2(u2h(w6.x), u2h(w7.x))));
        __half2 by = __hadd2(__hadd2(__hadd2(u2h(w0.y), u2h(w1.y)), __hadd2(u2h(w2.y), u2h(w3.y))),
                             __hadd2(__hadd2(u2h(w4.y), u2h(w5.y)), __hadd2(u2h(w6.y), u2h(w7.y))));
        float2 fbx = __half22float2(bx);
        float2 fby = __half22float2(by);
        accB.x += fbx.x; accB.y += fbx.y; accB.z += fby.x; accB.w += fby.y;
    }
    // remainder: one 8-edge group (segments are multiples of 8)
    for (; e < end; e += 8) {
        int4 i0 = *reinterpret_cast<const int4*>(&g_csrc[e]);
        int4 i1 = *reinterpret_cast<const int4*>(&g_csrc[e + 4]);
        uint2 v0 = __ldg(&y8[i0.x * 32 + lane]);
        uint2 v1 = __ldg(&y8[i0.y * 32 + lane]);
        uint2 v2 = __ldg(&y8[i0.z * 32 + lane]);
        uint2 v3 = __ldg(&y8[i0.w * 32 + lane]);
        uint2 v4 = __ldg(&y8[i1.x * 32 + lane]);
        uint2 v5 = __ldg(&y8[i1.y * 32 + lane]);
        uint2 v6 = __ldg(&y8[i1.z * 32 + lane]);
        uint2 v7 = __ldg(&y8[i1.w * 32 + lane]);
        __half2 ax = __hadd2(__hadd2(__hadd2(u2h(v0.x), u2h(v1.x)), __hadd2(u2h(v2.x), u2h(v3.x))),
                             __hadd2(__hadd2(u2h(v4.x), u2h(v5.x)), __hadd2(u2h(v6.x), u2h(v7.x))));
        __half2 ay = __hadd2(__hadd2(__hadd2(u2h(v0.y), u2h(v1.y)), __hadd2(u2h(v2.y), u2h(v3.y))),
                             __hadd2(__hadd2(u2h(v4.y), u2h(v5.y)), __hadd2(u2h(v6.y), u2h(v7.y))));
        float2 fax = __half22float2(ax);
        float2 fay = __half22float2(ay);
        accA.x += fax.x; accA.y += fax.y; accA.z += fay.x; accA.w += fay.y;
    }

    accA.x += accB.x; accA.y += accB.y; accA.z += accB.z; accA.w += accB.w;

    float4 b = bias ? reinterpret_cast<const float4*>(bias)[lane]
                    : make_float4(0.f, 0.f, 0.f, 0.f);
    float4 r;
    r.x = fmaf(di, accA.x, b.x);
    r.y = fmaf(di, accA.y, b.y);
    r.z = fmaf(di, accA.z, b.z);
    r.w = fmaf(di, accA.w, b.w);
    if (do_relu) {
        r.x = fmaxf(r.x, 0.f); r.y = fmaxf(r.y, 0.f);
        r.z = fmaxf(r.z, 0.f); r.w = fmaxf(r.w, 0.f);
    }
    float os = scale_out16 ? di : 1.f;
    uint2 o;
    *reinterpret_cast<__half2*>(&o.x) = __floats2half2_rn(os * r.x, os * r.y);
    *reinterpret_cast<__half2*>(&o.y) = __floats2half2_rn(os * r.z, os * r.w);
    reinterpret_cast<uint2*>(out16)[warp * 32 + lane] = o;
}

// ---------------- mean pool over sorted batch (fp16 input) --------------------
__global__ __launch_bounds__(128) void pool_kernel(const int* __restrict__ batch,
                                                   const __half* __restrict__ h)
{
    int g = blockIdx.x;
    __shared__ int s_beg, s_end;
    if (threadIdx.x == 0) {
        int lo = 0, hi = N_NODES;
        while (lo < hi) { int m = (lo + hi) >> 1; if (batch[m] < g) lo = m + 1; else hi = m; }
        s_beg = lo;
        lo = 0; hi = N_NODES;
        while (lo < hi) { int m = (lo + hi) >> 1; if (batch[m] < g + 1) lo = m + 1; else hi = m; }
        s_end = lo;
    }
    __syncthreads();
    int f = threadIdx.x;   // threads 0..63 each own one __half2 feature pair
    if (f < 64) {
        const __half2* h2 = reinterpret_cast<const __half2*>(h);
        float2 sum = make_float2(0.f, 0.f);
        for (int n = s_beg; n < s_end; n++) {
            float2 v = __half22float2(h2[n * 64 + f]);
            sum.x += v.x;
            sum.y += v.y;
        }
        float inv = 1.0f / fmaxf((float)(s_end - s_beg), 1.0f);
        g_s[g * 128 + f * 2]     = sum.x * inv;
        g_s[g * 128 + f * 2 + 1] = sum.y * inv;
    }
}

// ---------------- out[g,c] = s[g,:] @ WC[:,c] + bc[c] -------------------------
__global__ void out_kernel(float* __restrict__ out) {
    int t = blockIdx.x * blockDim.x + threadIdx.x;
    if (t < N_GRAPHS * N_CLASSES) {
        int g = t / N_CLASSES, c = t % N_CLASSES;
        float s = g_bc[c];
        for (int k = 0; k < HIDDEN; k++) s = fmaf(g_s[g * 128 + k], g_WC[k * N_CLASSES + c], s);
        out[t] = s;
    }
}

// ---------------- launcher ----------------------------------------------------
extern "C" void kernel_launch(void* const* d_in, const int* in_sizes, int n_in,
                              void* d_out, int out_size)
{
    const float* x     = (const float*)d_in[0];
    const int*   ei    = (const int*)  d_in[1];
    const int*   batch = (const int*)  d_in[2];
    const float* W1    = (const float*)d_in[3];
    const float* b1    = (const float*)d_in[4];
    const float* W2    = (const float*)d_in[5];
    const float* b2    = (const float*)d_in[6];
    const float* W3    = (const float*)d_in[7];
    const float* b3    = (const float*)d_in[8];
    const float* Wl    = (const float*)d_in[9];
    const float* bl    = (const float*)d_in[10];
    float* out = (float*)d_out;

    __half *y16, *h16;
    void* wfPtr;
    cudaGetSymbolAddress((void**)&y16, g_y16);
    cudaGetSymbolAddress((void**)&h16, g_h16);
    cudaGetSymbolAddress(&wfPtr, g_wf16);
    const uint4* wf1 = (const uint4*)wfPtr;
    const uint4* wf2 = wf1 + WF_PER_LAYER;

    const int AGG_BLOCKS = (N_NODES + 7) / 8;                 // 1 warp/node
    const int PREP_GRID  = 32 + PREF_BLOCKS + CNT_BLOCKS + 3 + 1;

    // prep (wfrag + csrc sentinel + deg count + head + zero rows)
    prep_kernel<<<PREP_GRID, 256>>>(W1, W2, W3, b3, Wl, bl, ei);
    // scan (mult-of-8 padded rowptr; re-zeroes deg)
    scan_kernel<<<1, 1024>>>();
    // GEMM1 (x fp32 -> fp16 staging, dinv epilogue) || CSR fill
    gemm1_fill_kernel<<<GEMM_BLOCKS + FILL_BLOCKS, 256>>>(x, wf1, y16, ei);

    // layer 1: gather y1' -> h1 fp16 (plain; gemm2 input)
    agg_kernel<<<AGG_BLOCKS, 256>>>(y16, h16, b1, 1, 0);
    // layer 2: gemm h1(fp16) -> y2' fp16 (dinv epilogue); gather -> h2' fp16 (pre-scaled)
    gemm_f16_kernel<<<GEMM_BLOCKS, 256>>>(h16, wf2, y16);
    agg_kernel<<<AGG_BLOCKS, 256>>>(y16, h16, b2, 1, 1);
    // layer 3 (reassociated): gather h2' -> z3 fp16 into y16 (free after agg2)
    agg_kernel<<<AGG_BLOCKS, 256>>>(h16, y16, (const float*)nullptr, 0, 0);

    // pool (fp16 input) + folded head
    pool_kernel<<<N_GRAPHS, 128>>>(batch, y16);
    out_kernel<<<(N_GRAPHS * N_CLASSES + 255) / 256, 256>>>(out);
}

// round 17
// speedup vs baseline: 1.1664x; 1.1664x over previous
#include <cuda_runtime.h>
#include <cuda_bf16.h>
#include <cuda_fp16.h>
#include <cstdint>

#define N_NODES 40000
#define N_EDGES 640000
#define HIDDEN  128
#define N_GRAPHS 256
#define N_CLASSES 5

#define GEMM_BLOCKS 313          // ceil(40000/128)
#define CNT_BLOCKS  625          // 640000/4/256
#define FILL_BLOCKS 1250         // 640000/2/256
#define CSR_CAP     (N_EDGES + 7 * N_NODES)   // segments padded to mult of 8 (920000)
#define WF_PER_LAYER 4096        // 8 ksteps x 16 ntiles x 32 lanes (uint4 each)
#define SCAN_BLOCKS 40           // 1024 nodes per block

// ---------------- scratch (static device globals; no runtime alloc) ----------
// NOTE: g_deg is zero at every launch entry: zero-initialized statically, and
// scanC re-zeroes it after consuming (deterministic across graph replays).
__device__ __align__(16) __half g_y16[(N_NODES + 1) * HIDDEN];  // y1'/y2'/z3 (+ zero row)
__device__ __align__(16) __half g_h16[(N_NODES + 1) * HIDDEN];  // h1 / h2' (+ zero row)
__device__ __align__(16) float  g_dinv[N_NODES];
__device__ __align__(16) int    g_deg[N_NODES];
__device__ __align__(16) int    g_rowptr[N_NODES + 4];
__device__ __align__(16) int    g_cursor[N_NODES];
__device__ __align__(16) int    g_csrc[CSR_CAP + 16];
__device__ int   g_bsum[SCAN_BLOCKS];       // per-block padded-degree sums
__device__ float g_s[N_GRAPHS * HIDDEN];    // pooled means
__device__ float g_WC[HIDDEN * N_CLASSES];  // W3 @ Wl
__device__ float g_bc[N_CLASSES];           // b3 @ Wl + bl
// fp16 W fragments for m16n8k16 MMA (W = hi + lo split), per layer:
// [ (ks*16 + nt)*32 + lane ] -> uint4 { b0_hi, b1_hi, b0_lo, b1_lo } (each = 2 halves)
__device__ __align__(16) uint4 g_wf16[2][WF_PER_LAYER];

// ---------------- helpers -----------------------------------------------------
__device__ __forceinline__ void mma_f16(float* d,
                                        unsigned a0, unsigned a1, unsigned a2, unsigned a3,
                                        unsigned b0, unsigned b1)
{
    asm volatile(
        "mma.sync.aligned.m16n8k16.row.col.f32.f16.f16.f32 "
        "{%0,%1,%2,%3}, {%4,%5,%6,%7}, {%8,%9}, {%0,%1,%2,%3};"
        : "+f"(d[0]), "+f"(d[1]), "+f"(d[2]), "+f"(d[3])
        : "r"(a0), "r"(a1), "r"(a2), "r"(a3), "r"(b0), "r"(b1));
}

__device__ __forceinline__ float2 h2f2(unsigned u) {
    __half2 h = *reinterpret_cast<__half2*>(&u);
    return __half22float2(h);
}

__device__ __forceinline__ __half2 u2h(unsigned u) {
    return *reinterpret_cast<__half2*>(&u);
}

__device__ __forceinline__ unsigned packh2(float a, float b) {
    __half2 h = __floats2half2_rn(a, b);     // a -> low half, b -> high half
    return *reinterpret_cast<unsigned*>(&h);
}

// ---------------- GEMM body: fp16 A (exact) x (W_hi + W_lo), fp32 acc ---------
// Y16 = half( dinv[row] * (A @ W) ).  A staged fp16 in smem (128x128, pad 8 halves).
__device__ __forceinline__ void gemm_body16(int bid,
                                            const float* __restrict__ A32,
                                            const __half* __restrict__ A16,
                                            const uint4* __restrict__ wfrag,
                                            __half* __restrict__ Y16)
{
    __shared__ __align__(16) unsigned s_a[128 * 68];   // fp16 tile: 68 words (136 halves)/row

    int tid  = threadIdx.x;
    int warp = tid >> 5;
    int lane = tid & 31;
    int row0 = bid * 128;
    int wrow = row0 + warp * 16;

    // stage A as fp16
    if (A32) {
        #pragma unroll
        for (int j = 0; j < 16; j++) {
            int idx = tid + 256 * j;            // 0..4095 float4s
            int r = idx >> 5;                   // 0..127
            int c4 = (idx & 31) * 4;            // 0..124 (halves/floats)
            int gr = row0 + r;
            float4 v = make_float4(0.f, 0.f, 0.f, 0.f);
            if (gr < N_NODES)
                v = *reinterpret_cast<const float4*>(&A32[gr * 128 + c4]);
            uint2 o;
            o.x = packh2(v.x, v.y);
            o.y = packh2(v.z, v.w);
            *reinterpret_cast<uint2*>(&s_a[r * 68 + (idx & 31) * 2]) = o;
        }
    } else {
        #pragma unroll
        for (int j = 0; j < 8; j++) {
            int idx = tid + 256 * j;            // 0..2047 uint4s
            int r = idx >> 4;                   // 0..127
            int c16 = idx & 15;                 // uint4 within row (8 halves each)
            int gr = row0 + r;
            uint4 v = make_uint4(0u, 0u, 0u, 0u);
            if (gr < N_NODES)
                v = *reinterpret_cast<const uint4*>(&A16[gr * 128 + c16 * 8]);
            *reinterpret_cast<uint4*>(&s_a[r * 68 + c16 * 4]) = v;
        }
    }
    __syncthreads();

    float acc[64];
    #pragma unroll
    for (int i = 0; i < 64; i++) acc[i] = 0.f;

    int rw0 = (warp * 16 + (lane >> 2)) * 68;
    int rw1 = rw0 + 8 * 68;

    #pragma unroll
    for (int ks = 0; ks < 8; ks++) {
        int cw = ks * 8 + (lane & 3);
        unsigned a0 = s_a[rw0 + cw];
        unsigned a1 = s_a[rw1 + cw];
        unsigned a2 = s_a[rw0 + cw + 4];
        unsigned a3 = s_a[rw1 + cw + 4];

        const uint4* bk = wfrag + ks * 512 + lane;
        #pragma unroll
        for (int nt = 0; nt < 16; nt++) {
            uint4 b = __ldg(bk + nt * 32);   // {b0_hi, b1_hi, b0_lo, b1_lo}
            float* d = acc + nt * 4;
            mma_f16(d, a0, a1, a2, a3, b.x, b.y);   // A x W_hi
            mma_f16(d, a0, a1, a2, a3, b.z, b.w);   // A x W_lo
        }
    }

    if (wrow < N_NODES) {
        int r0 = wrow + (lane >> 2);
        int r1 = r0 + 8;
        float d0 = g_dinv[r0];
        float d1 = g_dinv[r1];
        #pragma unroll
        for (int nt = 0; nt < 16; nt++) {
            int col = nt * 8 + (lane & 3) * 2;
            __half2 p0 = __floats2half2_rn(d0 * acc[nt * 4 + 0], d0 * acc[nt * 4 + 1]);
            __half2 p1 = __floats2half2_rn(d1 * acc[nt * 4 + 2], d1 * acc[nt * 4 + 3]);
            *reinterpret_cast<__half2*>(&Y16[r0 * 128 + col]) = p0;
            *reinterpret_cast<__half2*>(&Y16[r1 * 128 + col]) = p1;
        }
    }
}

// ---------------- prep: wfrag + deg count + head fold + zero rows -------------
__global__ __launch_bounds__(256) void prep_kernel(
    const float* __restrict__ W1, const float* __restrict__ W2,
    const float* __restrict__ W3, const float* __restrict__ b3,
    const float* __restrict__ Wl, const float* __restrict__ bl,
    const int* __restrict__ ei)
{
    const int B_CNT  = 32;                       // 2 layers x 4096 frags / 256
    const int B_HEAD = B_CNT + CNT_BLOCKS;
    const int B_ZROW = B_HEAD + 3;

    if (blockIdx.x < 32) {
        int t = blockIdx.x * 256 + threadIdx.x;  // 0..8191
        int layer = t >> 12;
        int r = t & 4095;                 // (ks*16 + nt)*32 + lane
        int ks   = r >> 9;                // 0..7
        int nt   = (r >> 5) & 15;
        int lane = r & 31;
        int k0 = ks * 16 + (lane & 3) * 2;
        int n  = nt * 8 + (lane >> 2);
        const float* W = layer ? W2 : W1;
        float w00 = W[k0 * HIDDEN + n];
        float w01 = W[(k0 + 1) * HIDDEN + n];
        float w10 = W[(k0 + 8) * HIDDEN + n];
        float w11 = W[(k0 + 9) * HIDDEN + n];
        float h00 = __half2float(__float2half_rn(w00));
        float h01 = __half2float(__float2half_rn(w01));
        float h10 = __half2float(__float2half_rn(w10));
        float h11 = __half2float(__float2half_rn(w11));
        uint4 o;
        o.x = packh2(h00, h01);
        o.y = packh2(h10, h11);
        o.z = packh2(w00 - h00, w01 - h01);
        o.w = packh2(w10 - h10, w11 - h11);
        g_wf16[layer][r] = o;
    } else if (blockIdx.x < B_HEAD) {
        int e4 = ((blockIdx.x - B_CNT) * 256 + threadIdx.x) * 4;
        if (e4 < N_EDGES) {
            int4 d = *reinterpret_cast<const int4*>(&ei[N_EDGES + e4]);
            atomicAdd(&g_deg[d.x], 1);
            atomicAdd(&g_deg[d.y], 1);
            atomicAdd(&g_deg[d.z], 1);
            atomicAdd(&g_deg[d.w], 1);
        }
    } else if (blockIdx.x < B_ZROW) {
        int t = (blockIdx.x - B_HEAD) * 256 + threadIdx.x;
        if (t < HIDDEN * N_CLASSES) {
            int j = t / N_CLASSES, c = t % N_CLASSES;
            float s = 0.f;
            for (int k = 0; k < HIDDEN; k++) s = fmaf(W3[j * HIDDEN + k], Wl[k * N_CLASSES + c], s);
            g_WC[t] = s;
        } else if (t < HIDDEN * N_CLASSES + N_CLASSES) {
            int c = t - HIDDEN * N_CLASSES;
            float s = bl[c];
            for (int k = 0; k < HIDDEN; k++) s = fmaf(b3[k], Wl[k * N_CLASSES + c], s);
            g_bc[c] = s;
        }
    } else {
        // zero the sentinel rows (row N_NODES) of both fp16 gather buffers
        int t = threadIdx.x;
        if (t < 64)
            reinterpret_cast<unsigned*>(&g_y16[N_NODES * HIDDEN])[t] = 0u;
        else if (t < 128)
            reinterpret_cast<unsigned*>(&g_h16[N_NODES * HIDDEN])[t - 64] = 0u;
    }
}

// ---------------- scanA: per-block padded-degree sums (1024 nodes/block) ------
__global__ __launch_bounds__(256) void scanA_kernel() {
    int tid = threadIdx.x;
    int i4 = blockIdx.x * 1024 + tid * 4;
    int s = 0;
    if (i4 < N_NODES) {
        int4 v = *reinterpret_cast<const int4*>(&g_deg[i4]);
        s = ((v.x + 7) & ~7) + ((v.y + 7) & ~7) + ((v.z + 7) & ~7) + ((v.w + 7) & ~7);
    }
    // block reduce
    __shared__ int wsum[8];
    int lane = tid & 31, wid = tid >> 5;
    #pragma unroll
    for (int d = 16; d > 0; d >>= 1) s += __shfl_down_sync(0xffffffffu, s, d);
    if (lane == 0) wsum[wid] = s;
    __syncthreads();
    if (wid == 0) {
        int w = (lane < 8) ? wsum[lane] : 0;
        #pragma unroll
        for (int d = 4; d > 0; d >>= 1) w += __shfl_down_sync(0xffffffffu, w, d);
        if (lane == 0) g_bsum[blockIdx.x] = w;
    }
}

// ---------------- scanC: block-local scan + rowptr/cursor/dinv/sentinels ------
// Re-zeroes g_deg (launch-entry invariant). Writes sentinel pads into g_csrc.
__global__ __launch_bounds__(256) void scanC_kernel() {
    int tid = threadIdx.x;
    int lane = tid & 31, wid = tid >> 5;
    __shared__ int s_bs[SCAN_BLOCKS];
    __shared__ int s_off;
    __shared__ int wsum[8];

    if (tid < SCAN_BLOCKS) s_bs[tid] = g_bsum[tid];
    __syncthreads();
    if (tid == 0) {
        int o = 0;
        for (int j = 0; j < blockIdx.x; j++) o += s_bs[j];
        s_off = o;
    }
    __syncthreads();

    int i4 = blockIdx.x * 1024 + tid * 4;
    int4 v = make_int4(0, 0, 0, 0);
    if (i4 < N_NODES)
        v = *reinterpret_cast<const int4*>(&g_deg[i4]);
    int4 p = make_int4((v.x + 7) & ~7, (v.y + 7) & ~7,
                       (v.z + 7) & ~7, (v.w + 7) & ~7);
    int s = p.x + p.y + p.z + p.w;
    int x = s;
    #pragma unroll
    for (int d = 1; d < 32; d <<= 1) {
        int t = __shfl_up_sync(0xffffffffu, x, d);
        if (lane >= d) x += t;
    }
    if (lane == 31) wsum[wid] = x;
    __syncthreads();
    if (wid == 0 && lane < 8) {
        int w = wsum[lane];
        #pragma unroll
        for (int d = 1; d < 8; d <<= 1) {
            int t = __shfl_up_sync(0x000000ffu, w, d);
            if (lane >= d) w += t;
        }
        wsum[lane] = w;
    }
    __syncthreads();
    int woff = (wid == 0) ? 0 : wsum[wid - 1];
    int incl = x + woff;                   // inclusive within block
    int e0 = incl - s + s_off;             // exclusive global start for this thread's 4
    if (i4 < N_NODES) {
        int4 rp = make_int4(e0, e0 + p.x, e0 + p.x + p.y, e0 + p.x + p.y + p.z);
        *reinterpret_cast<int4*>(&g_rowptr[i4]) = rp;
        *reinterpret_cast<int4*>(&g_cursor[i4]) = rp;
        float4 dv = make_float4(rsqrtf((float)(v.x + 1)), rsqrtf((float)(v.y + 1)),
                                rsqrtf((float)(v.z + 1)), rsqrtf((float)(v.w + 1)));
        *reinterpret_cast<float4*>(&g_dinv[i4]) = dv;
        *reinterpret_cast<int4*>(&g_deg[i4]) = make_int4(0, 0, 0, 0);
        // sentinel padding: slots [rp+deg, rp+pad) -> zero row
        for (int q = v.x; q < p.x; q++) g_csrc[rp.x + q] = N_NODES;
        for (int q = v.y; q < p.y; q++) g_csrc[rp.y + q] = N_NODES;
        for (int q = v.z; q < p.z; q++) g_csrc[rp.z + q] = N_NODES;
        for (int q = v.w; q < p.w; q++) g_csrc[rp.w + q] = N_NODES;
    }
    if (blockIdx.x == SCAN_BLOCKS - 1 && tid == 255)
        g_rowptr[N_NODES] = s_off + incl;
}

// ---------------- fused: GEMM layer-1 (x fp32 -> fp16) + CSR fill -------------
__global__ __launch_bounds__(256) void gemm1_fill_kernel(
    const float* __restrict__ A, const uint4* __restrict__ wfrag,
    __half* __restrict__ Y16, const int* __restrict__ ei)
{
    if (blockIdx.x < GEMM_BLOCKS) {
        gemm_body16(blockIdx.x, A, (const __half*)nullptr, wfrag, Y16);
    } else {
        int e2 = ((blockIdx.x - GEMM_BLOCKS) * 256 + threadIdx.x) * 2;
        if (e2 < N_EDGES) {
            int2 s = *reinterpret_cast<const int2*>(&ei[e2]);
            int2 d = *reinterpret_cast<const int2*>(&ei[N_EDGES + e2]);
            int p0 = atomicAdd(&g_cursor[d.x], 1);
            int p1 = atomicAdd(&g_cursor[d.y], 1);
            g_csrc[p0] = s.x;
            g_csrc[p1] = s.y;
        }
    }
}

// ---------------- standalone GEMM (layer 2, fp16 input) -----------------------
__global__ __launch_bounds__(256) void gemm_f16_kernel(
    const __half* __restrict__ A16, const uint4* __restrict__ wfrag,
    __half* __restrict__ Y16)
{
    gemm_body16(blockIdx.x, (const float*)nullptr, A16, wfrag, Y16);
}

// ---------------- Aggregation: 8-edge pairwise fp16 tree, fp32 accumulate -----
// Rows pre-scaled by dinv[src]:  r = dinv[i] * (self + sum_in row[s]) + b
// out16: fp16 result, times dinv[i] iff scale_out16.
__global__ __launch_bounds__(256) void agg_kernel(
    const __half* __restrict__ y16, __half* __restrict__ out16,
    const float* __restrict__ bias, int do_relu, int scale_out16)
{
    int warp = (blockIdx.x * blockDim.x + threadIdx.x) >> 5;
    int lane = threadIdx.x & 31;
    if (warp >= N_NODES) return;

    const uint2* y8 = reinterpret_cast<const uint2*>(y16);   // 4 halves per lane
    float di = g_dinv[warp];

    uint2 sv = y8[warp * 32 + lane];
    float2 sa = h2f2(sv.x), sb = h2f2(sv.y);
    float4 acc = make_float4(sa.x, sa.y, sb.x, sb.y);

    int e   = g_rowptr[warp];
    int end = g_rowptr[warp + 1];

    for (; e < end; e += 8) {
        int4 i0 = *reinterpret_cast<const int4*>(&g_csrc[e]);
        int4 i1 = *reinterpret_cast<const int4*>(&g_csrc[e + 4]);
        uint2 v0 = __ldg(&y8[i0.x * 32 + lane]);
        uint2 v1 = __ldg(&y8[i0.y * 32 + lane]);
        uint2 v2 = __ldg(&y8[i0.z * 32 + lane]);
        uint2 v3 = __ldg(&y8[i0.w * 32 + lane]);
        uint2 v4 = __ldg(&y8[i1.x * 32 + lane]);
        uint2 v5 = __ldg(&y8[i1.y * 32 + lane]);
        uint2 v6 = __ldg(&y8[i1.z * 32 + lane]);
        uint2 v7 = __ldg(&y8[i1.w * 32 + lane]);
        __half2 x01 = __hadd2(u2h(v0.x), u2h(v1.x));
        __half2 x23 = __hadd2(u2h(v2.x), u2h(v3.x));
        __half2 x45 = __hadd2(u2h(v4.x), u2h(v5.x));
        __half2 x67 = __hadd2(u2h(v6.x), u2h(v7.x));
        __half2 xs  = __hadd2(__hadd2(x01, x23), __hadd2(x45, x67));
        __half2 y01 = __hadd2(u2h(v0.y), u2h(v1.y));
        __half2 y23 = __hadd2(u2h(v2.y), u2h(v3.y));
        __half2 y45 = __hadd2(u2h(v4.y), u2h(v5.y));
        __half2 y67 = __hadd2(u2h(v6.y), u2h(v7.y));
        __half2 ys  = __hadd2(__hadd2(y01, y23), __hadd2(y45, y67));
        float2 fx = __half22float2(xs);
        float2 fy = __half22float2(ys);
        acc.x += fx.x; acc.y += fx.y; acc.z += fy.x; acc.w += fy.y;
    }

    float4 b = bias ? reinterpret_cast<const float4*>(bias)[lane]
                    : make_float4(0.f, 0.f, 0.f, 0.f);
    float4 r;
    r.x = fmaf(di, acc.x, b.x);
    r.y = fmaf(di, acc.y, b.y);
    r.z = fmaf(di, acc.z, b.z);
    r.w = fmaf(di, acc.w, b.w);
    if (do_relu) {
        r.x = fmaxf(r.x, 0.f); r.y = fmaxf(r.y, 0.f);
        r.z = fmaxf(r.z, 0.f); r.w = fmaxf(r.w, 0.f);
    }
    float os = scale_out16 ? di : 1.f;
    uint2 o;
    *reinterpret_cast<__half2*>(&o.x) = __floats2half2_rn(os * r.x, os * r.y);
    *reinterpret_cast<__half2*>(&o.y) = __floats2half2_rn(os * r.z, os * r.w);
    reinterpret_cast<uint2*>(out16)[warp * 32 + lane] = o;
}

// ---------------- mean pool over sorted batch (fp16 input) --------------------
__global__ __launch_bounds__(128) void pool_kernel(const int* __restrict__ batch,
                                                   const __half* __restrict__ h)
{
    int g = blockIdx.x;
    __shared__ int s_beg, s_end;
    if (threadIdx.x == 0) {
        int lo = 0, hi = N_NODES;
        while (lo < hi) { int m = (lo + hi) >> 1; if (batch[m] < g) lo = m + 1; else hi = m; }
        s_beg = lo;
        lo = 0; hi = N_NODES;
        while (lo < hi) { int m = (lo + hi) >> 1; if (batch[m] < g + 1) lo = m + 1; else hi = m; }
        s_end = lo;
    }
    __syncthreads();
    int f = threadIdx.x;   // threads 0..63 each own one __half2 feature pair
    if (f < 64) {
        const __half2* h2 = reinterpret_cast<const __half2*>(h);
        float2 sum = make_float2(0.f, 0.f);
        for (int n = s_beg; n < s_end; n++) {
            float2 v = __half22float2(h2[n * 64 + f]);
            sum.x += v.x;
            sum.y += v.y;
        }
        float inv = 1.0f / fmaxf((float)(s_end - s_beg), 1.0f);
        g_s[g * 128 + f * 2]     = sum.x * inv;
        g_s[g * 128 + f * 2 + 1] = sum.y * inv;
    }
}

// ---------------- out[g,c] = s[g,:] @ WC[:,c] + bc[c] -------------------------
__global__ void out_kernel(float* __restrict__ out) {
    int t = blockIdx.x * blockDim.x + threadIdx.x;
    if (t < N_GRAPHS * N_CLASSES) {
        int g = t / N_CLASSES, c = t % N_CLASSES;
        float s = g_bc[c];
        for (int k = 0; k < HIDDEN; k++) s = fmaf(g_s[g * 128 + k], g_WC[k * N_CLASSES + c], s);
        out[t] = s;
    }
}

// ---------------- launcher ----------------------------------------------------
extern "C" void kernel_launch(void* const* d_in, const int* in_sizes, int n_in,
                              void* d_out, int out_size)
{
    const float* x     = (const float*)d_in[0];
    const int*   ei    = (const int*)  d_in[1];
    const int*   batch = (const int*)  d_in[2];
    const float* W1    = (const float*)d_in[3];
    const float* b1    = (const float*)d_in[4];
    const float* W2    = (const float*)d_in[5];
    const float* b2    = (const float*)d_in[6];
    const float* W3    = (const float*)d_in[7];
    const float* b3    = (const float*)d_in[8];
    const float* Wl    = (const float*)d_in[9];
    const float* bl    = (const float*)d_in[10];
    float* out = (float*)d_out;

    __half *y16, *h16;
    void* wfPtr;
    cudaGetSymbolAddress((void**)&y16, g_y16);
    cudaGetSymbolAddress((void**)&h16, g_h16);
    cudaGetSymbolAddress(&wfPtr, g_wf16);
    const uint4* wf1 = (const uint4*)wfPtr;
    const uint4* wf2 = wf1 + WF_PER_LAYER;

    const int AGG_BLOCKS = (N_NODES + 7) / 8;                 // 1 warp/node
    const int PREP_GRID  = 32 + CNT_BLOCKS + 3 + 1;

    // prep (wfrag + deg count + head + zero rows)
    prep_kernel<<<PREP_GRID, 256>>>(W1, W2, W3, b3, Wl, bl, ei);
    // parallel scan: block sums, then rowptr/cursor/dinv + sentinel pads
    scanA_kernel<<<SCAN_BLOCKS, 256>>>();
    scanC_kernel<<<SCAN_BLOCKS, 256>>>();
    // GEMM1 (x fp32 -> fp16 staging, dinv epilogue) || CSR fill
    gemm1_fill_kernel<<<GEMM_BLOCKS + FILL_BLOCKS, 256>>>(x, wf1, y16, ei);

    // layer 1: gather y1' -> h1 fp16 (plain; gemm2 input)
    agg_kernel<<<AGG_BLOCKS, 256>>>(y16, h16, b1, 1, 0);
    // layer 2: gemm h1(fp16) -> y2' fp16 (dinv epilogue); gather -> h2' fp16 (pre-scaled)
    gemm_f16_kernel<<<GEMM_BLOCKS, 256>>>(h16, wf2, y16);
    agg_kernel<<<AGG_BLOCKS, 256>>>(y16, h16, b2, 1, 1);
    // layer 3 (reassociated): gather h2' -> z3 fp16 into y16 (free after agg2)
    agg_kernel<<<AGG_BLOCKS, 256>>>(h16, y16, (const float*)nullptr, 0, 0);

    // pool (fp16 input) + folded head
    pool_kernel<<<N_GRAPHS, 128>>>(batch, y16);
    out_kernel<<<(N_GRAPHS * N_CLASSES + 255) / 256, 256>>>(out);
}